// round 4
// baseline (speedup 1.0000x reference)
#include <cuda_runtime.h>
#include <math.h>

#define NN 6000
#define NE 72000
#define PP 2
#define MM 9
#define FF 64
#define HH 4
#define CDIM 1664
#define NF 256
#define NPMF (NN*PP*MM*FF)

#define OFF_G1 0
#define OFF_B1 384
#define OFF_A1 448
#define OFF_G2 832
#define OFF_B2 1216
#define OFF_A2 1280

typedef unsigned long long u64;

__constant__ int c_deg[9] = {0,1,1,1,2,2,2,2,2};

// ---- scratch (static device globals; no runtime allocation) ----
__device__ float    g_c[NN*CDIM];
__device__ __align__(16) float g_xpre[NPMF];
__device__ __align__(16) float g_q[NPMF];
__device__ __align__(16) float g_k[NPMF];
__device__ __align__(16) float g_v[NPMF];
__device__ float    g_logits[NE*HH];
__device__ unsigned g_lmax[NN*HH];
__device__ float    g_w[NE*HH];
__device__ float    g_denom[NN*HH];
__device__ float    g_sumcut[NN];
__device__ float    g_cnt[NN];
__device__ __align__(16) float g_att[NPMF];
__device__ float    g_x1[NPMF];
__device__ __align__(16) float g_xpre2[NPMF];
__device__ float    g_gate[NN*NF];

// transposed weights (reduction dim contiguous for f32x2 packing)
__device__ __align__(16) float g_WqT[18*4096];
__device__ __align__(16) float g_WkT[18*4096];
__device__ __align__(16) float g_WvT[18*4096];
__device__ __align__(16) float g_WoT[18*4096];
__device__ __align__(16) float g_WeqkT[4096];
__device__ __align__(16) float g_WevT[4096];
__device__ __align__(16) float g_W1T[18*16384];   // [pl][j][f]
__device__ __align__(16) float g_W2T[18*16384];   // [pl][g][jj]
__device__ __align__(16) float g_WcT[CDIM*64];    // [j][t]

__device__ __forceinline__ void fma2(u64 &d, u64 a, u64 b){
    asm("fma.rn.f32x2 %0, %1, %2, %0;" : "+l"(d) : "l"(a), "l"(b));
}
__device__ __forceinline__ float hsum2(u64 a){
    return __uint_as_float((unsigned)a) + __uint_as_float((unsigned)(a>>32));
}
__device__ __forceinline__ unsigned flipf(float f){
    unsigned u = __float_as_uint(f);
    return (u & 0x80000000u) ? ~u : (u | 0x80000000u);
}
__device__ __forceinline__ float unflipf(unsigned u){
    return __uint_as_float((u & 0x80000000u) ? (u ^ 0x80000000u) : ~u);
}

// ---------------- weight transposes (prep) ----------------
__global__ void k_tr_qkvo(const float* __restrict__ Wq, const float* __restrict__ Wk,
                          const float* __restrict__ Wv, const float* __restrict__ Wo){
    const float* s; float* d;
    if (blockIdx.y == 0){ s = Wq; d = g_WqT; }
    else if (blockIdx.y == 1){ s = Wk; d = g_WkT; }
    else if (blockIdx.y == 2){ s = Wv; d = g_WvT; }
    else { s = Wo; d = g_WoT; }
    s += blockIdx.x*4096; d += blockIdx.x*4096;
    for (int i = threadIdx.x; i < 4096; i += 256){
        int f = i>>6, g = i&63; d[g*64+f] = s[i];
    }
}
__global__ void k_tr_e(const float* __restrict__ Weqk, const float* __restrict__ Wev){
    const float* s = blockIdx.x ? Wev : Weqk;
    float* d = blockIdx.x ? g_WevT : g_WeqkT;
    for (int i = threadIdx.x; i < 4096; i += 256){
        int f = i>>6, g = i&63; d[g*64+f] = s[i];
    }
}
__global__ void k_tr_w1(const float* __restrict__ W1){
    const float* s = W1 + blockIdx.x*16384; float* d = g_W1T + blockIdx.x*16384;
    for (int i = threadIdx.x; i < 16384; i += 256){
        int f = i>>8, j = i&255; d[j*64+f] = s[i];
    }
}
__global__ void k_tr_w2(const float* __restrict__ W2){
    const float* s = W2 + blockIdx.x*16384; float* d = g_W2T + blockIdx.x*16384;
    for (int i = threadIdx.x; i < 16384; i += 256){
        int jj = i>>6, g = i&63; d[g*256+jj] = s[i];
    }
}
__global__ void k_tr_wc(const float* __restrict__ Wc){
    int i = blockIdx.x*256 + threadIdx.x;
    if (i < 64*CDIM){
        int t = i/CDIM, j = i - t*CDIM;
        g_WcT[j*64+t] = Wc[i];
    }
}

// ---------------- init ----------------
__global__ void k_init(){
    int i = blockIdx.x*256 + threadIdx.x;
    if (i < NPMF) g_att[i] = 0.f;
    if (i < NN*HH){ g_denom[i] = 0.f; g_lmax[i] = 0u; }
    if (i < NN){ g_sumcut[i] = 0.f; g_cnt[i] = 0.f; }
}

// ---------------- time conditioning: LN(T) -> silu -> @W_c + b_c ----------------
__global__ void k_timecond(const float* __restrict__ ft, const float* __restrict__ scale,
                           const float* __restrict__ bias, const float* __restrict__ bc){
    __shared__ __align__(16) float s[8][64];
    int n0 = blockIdx.x*8;
    int tid = threadIdx.x; // 256
    for (int i = tid; i < 512; i += 256){
        int nn = i>>6, f = i&63; int n = n0+nn;
        s[nn][f] = (n < NN) ? ft[n*64+f] : 0.f;
    }
    __syncthreads();
    int w = tid>>5, lane = tid&31;
    {
        float v0 = s[w][lane], v1 = s[w][lane+32];
        float sum = v0+v1, sq = v0*v0 + v1*v1;
        #pragma unroll
        for (int o = 16; o; o >>= 1){
            sum += __shfl_xor_sync(0xffffffffu, sum, o);
            sq  += __shfl_xor_sync(0xffffffffu, sq , o);
        }
        float mu = sum*(1.f/64.f);
        float var = sq*(1.f/64.f) - mu*mu;
        float rstd = rsqrtf(var + 1e-6f);
        float c0 = (v0-mu)*rstd*scale[lane]    + bias[lane];
        float c1 = (v1-mu)*rstd*scale[lane+32] + bias[lane+32];
        s[w][lane]    = c0 / (1.f + __expf(-c0));
        s[w][lane+32] = c1 / (1.f + __expf(-c1));
    }
    __syncthreads();
    for (int j = tid; j < CDIM; j += 256){
        u64 acc[8];
        #pragma unroll
        for (int nn = 0; nn < 8; nn++) acc[nn] = 0ull;
        const ulonglong2* wp = (const ulonglong2*)&g_WcT[j*64];
        for (int t4 = 0; t4 < 16; t4++){
            ulonglong2 wv = wp[t4];
            #pragma unroll
            for (int nn = 0; nn < 8; nn++){
                ulonglong2 x = *(const ulonglong2*)&s[nn][t4*4];
                fma2(acc[nn], x.x, wv.x);
                fma2(acc[nn], x.y, wv.y);
            }
        }
        float bb = bc[j];
        #pragma unroll
        for (int nn = 0; nn < 8; nn++){
            int n = n0+nn;
            if (n < NN) g_c[(size_t)n*CDIM + j] = hsum2(acc[nn]) + bb;
        }
    }
}

// ---------------- equivariant LN + modulate ----------------
template<int PASS>
__global__ void k_ln_mod(const float* __restrict__ fn){
    int n = blockIdx.x;
    const float* xin  = PASS ? g_x1 : fn;
    float*       xout = PASS ? g_xpre2 : g_xpre;
    const int offG = PASS ? OFF_G2 : OFF_G1;
    const int offB = PASS ? OFF_B2 : OFF_B1;
    __shared__ float sm[1152];
    __shared__ float s_inv[2][3];
    __shared__ float s_mean[2];
    int tid = threadIdx.x; // 192
    for (int i = tid; i < 1152; i += 192) sm[i] = xin[(size_t)n*1152 + i];
    __syncthreads();
    int w = tid>>5, lane = tid&31;
    if (w < 6){
        int p = w/3, l = w - 3*p;
        int base = p*576 + l*l*64;
        int cnt = (2*l+1)*64;
        float ss = 0.f, s1 = 0.f;
        for (int i = lane; i < cnt; i += 32){ float v = sm[base+i]; ss += v*v; s1 += v; }
        #pragma unroll
        for (int o = 16; o; o >>= 1){
            ss += __shfl_xor_sync(0xffffffffu, ss, o);
            s1 += __shfl_xor_sync(0xffffffffu, s1, o);
        }
        if (lane == 0){
            if (l == 0){ float mean = s1*(1.f/64.f); s_mean[p] = mean; ss -= 64.f*mean*mean; }
            s_inv[p][l] = rsqrtf(ss/(float)cnt + 1e-6f);
        }
    }
    __syncthreads();
    const float* cc = g_c + (size_t)n*CDIM;
    for (int i = tid; i < 1152; i += 192){
        int p2 = i/576; int r = i - 576*p2; int m = r>>6; int f = r&63;
        int l2 = c_deg[m];
        float v = sm[i];
        if (m == 0) v -= s_mean[p2];
        float gmod = cc[offG + (p2*3+l2)*64 + f];
        float y = v * s_inv[p2][l2] * (1.f + gmod);
        if (m == 0) y += cc[offB + f];
        xout[(size_t)n*1152 + i] = y;
    }
}

// ---------------- QKV projections, packed f32x2 over f ----------------
__global__ void k_qkv(){
    int n0 = blockIdx.x*16;
    int pm = blockIdx.y; int p = pm/9, m = pm - 9*p; int l = c_deg[m];
    __shared__ __align__(16) float xs[16*64];
    int tid = threadIdx.x; // 256
    for (int i = tid; i < 1024; i += 256){
        int nn = i>>6, f = i&63; int n = n0+nn;
        xs[i] = (n < NN) ? g_xpre[((size_t)(n*PP+p)*MM+m)*FF + f] : 0.f;
    }
    __syncthreads();
    int g = tid&63, nb = tid>>6;
    size_t wbase = (size_t)(p*3+l)*4096 + g*64;
    const ulonglong2* wq = (const ulonglong2*)&g_WqT[wbase];
    const ulonglong2* wk = (const ulonglong2*)&g_WkT[wbase];
    const ulonglong2* wv = (const ulonglong2*)&g_WvT[wbase];
    u64 aq[4] = {0,0,0,0}, ak[4] = {0,0,0,0}, av[4] = {0,0,0,0};
    for (int f4 = 0; f4 < 16; f4++){
        ulonglong2 q2 = wq[f4], k2 = wk[f4], v2 = wv[f4];
        #pragma unroll
        for (int j = 0; j < 4; j++){
            ulonglong2 x = *(const ulonglong2*)&xs[(nb+4*j)*64 + f4*4];
            fma2(aq[j], x.x, q2.x); fma2(aq[j], x.y, q2.y);
            fma2(ak[j], x.x, k2.x); fma2(ak[j], x.y, k2.y);
            fma2(av[j], x.x, v2.x); fma2(av[j], x.y, v2.y);
        }
    }
    #pragma unroll
    for (int j = 0; j < 4; j++){
        int n = n0 + nb + 4*j;
        if (n < NN){
            int idx = ((n*PP+p)*MM+m)*FF + g;
            g_q[idx] = hsum2(aq[j]); g_k[idx] = hsum2(ak[j]); g_v[idx] = hsum2(av[j]);
        }
    }
}

// ---------------- per-edge: e_qk projection + logits + segment max ----------------
__global__ void k_logits(const float* __restrict__ fe,
                         const int* __restrict__ src, const int* __restrict__ dst){
    int e = blockIdx.x;
    __shared__ __align__(16) float sfe[576];
    __shared__ __align__(16) float seqk[576];
    int tid = threadIdx.x; // 128
    const float4* fp = (const float4*)(fe + (size_t)e*576);
    for (int i = tid; i < 144; i += 128) ((float4*)sfe)[i] = fp[i];
    __syncthreads();
    {
        int g = tid&63, half = tid>>6;
        int m0 = half*5;
        const ulonglong2* wt = (const ulonglong2*)&g_WeqkT[g*64];
        u64 acc[5] = {0,0,0,0,0};
        for (int f4 = 0; f4 < 16; f4++){
            ulonglong2 wv = wt[f4];
            #pragma unroll
            for (int mi = 0; mi < 5; mi++){
                int m = m0+mi;
                if (m < 9){
                    ulonglong2 x = *(const ulonglong2*)&sfe[m*64 + f4*4];
                    fma2(acc[mi], x.x, wv.x); fma2(acc[mi], x.y, wv.y);
                }
            }
        }
        #pragma unroll
        for (int mi = 0; mi < 5; mi++){
            int m = m0+mi;
            if (m < 9) seqk[m*64+g] = hsum2(acc[mi]);
        }
    }
    __syncthreads();
    int h = tid>>5, lane = tid&31;
    int s = src[e], d = dst[e];
    float acc = 0.f;
    int f = h*16 + (lane&15);
    for (int pm = (lane>>4); pm < 18; pm += 2){
        int p = pm/9, m = pm - 9*p;
        int off = ((p)*MM+m)*FF + f;
        acc += g_q[(size_t)d*1152 + off] * g_k[(size_t)s*1152 + off] * seqk[m*64+f];
    }
    #pragma unroll
    for (int o = 16; o; o >>= 1) acc += __shfl_xor_sync(0xffffffffu, acc, o);
    if (lane == 0){
        float lg = acc * 0.05892556509887896f;  // 1/sqrt(288)
        g_logits[e*HH + h] = lg;
        atomicMax(&g_lmax[d*HH + h], flipf(lg));
    }
}

// ---------------- softmax weights + segment sums ----------------
__global__ void k_softmax_w(const int* __restrict__ dst, const float* __restrict__ cutoff){
    int e = blockIdx.x*256 + threadIdx.x;
    if (e >= NE) return;
    int d = dst[e];
    float cut = cutoff[e];
    #pragma unroll
    for (int h = 0; h < HH; h++){
        float lg = g_logits[e*HH + h];
        float lm = unflipf(g_lmax[d*HH + h]);
        float w = __expf(lg - lm) * cut;
        g_w[e*HH + h] = w;
        atomicAdd(&g_denom[d*HH + h], w);
    }
    atomicAdd(&g_sumcut[d], cut);
    atomicAdd(&g_cnt[d], 1.f);
}

// ---------------- per-edge: e_v projection + attn*v scatter (v4 red) ----------------
__global__ void k_scatter(const float* __restrict__ fe,
                          const int* __restrict__ src, const int* __restrict__ dst){
    int e = blockIdx.x;
    __shared__ __align__(16) float sfe[576];
    __shared__ __align__(16) float sev[576];
    __shared__ float satt[4];
    int tid = threadIdx.x; // 128
    const float4* fp = (const float4*)(fe + (size_t)e*576);
    for (int i = tid; i < 144; i += 128) ((float4*)sfe)[i] = fp[i];
    int d = dst[e], s = src[e];
    if (tid < 4) satt[tid] = g_w[e*HH + tid] / (g_denom[d*HH + tid] + 1e-9f);
    __syncthreads();
    {
        int g = tid&63, half = tid>>6;
        int m0 = half*5;
        const ulonglong2* wt = (const ulonglong2*)&g_WevT[g*64];
        u64 acc[5] = {0,0,0,0,0};
        for (int f4 = 0; f4 < 16; f4++){
            ulonglong2 wv = wt[f4];
            #pragma unroll
            for (int mi = 0; mi < 5; mi++){
                int m = m0+mi;
                if (m < 9){
                    ulonglong2 x = *(const ulonglong2*)&sfe[m*64 + f4*4];
                    fma2(acc[mi], x.x, wv.x); fma2(acc[mi], x.y, wv.y);
                }
            }
        }
        #pragma unroll
        for (int mi = 0; mi < 5; mi++){
            int m = m0+mi;
            if (m < 9) sev[m*64+g] = hsum2(acc[mi]);
        }
    }
    __syncthreads();
    for (int i4 = tid; i4 < 288; i4 += 128){
        int i = i4*4;
        int p = i/576; int r = i - 576*p; int m = r>>6; int f = r&63; int h = f>>4;
        float4 vv = *(const float4*)&g_v[((size_t)(s*PP+p)*MM+m)*FF + f];
        float4 ev = *(const float4*)&sev[m*64+f];
        float a = satt[h];
        float* op = &g_att[((size_t)(d*PP+p)*MM+m)*FF + f];
        float r0 = a*vv.x*ev.x, r1 = a*vv.y*ev.y, r2 = a*vv.z*ev.z, r3 = a*vv.w*ev.w;
        asm volatile("red.global.add.v4.f32 [%0], {%1,%2,%3,%4};"
                     :: "l"(op), "f"(r0), "f"(r1), "f"(r2), "f"(r3) : "memory");
    }
}

// ---------------- Wo projection + mean_cut select + residual 1 ----------------
__global__ void k_out_res(const float* __restrict__ fn){
    int n0 = blockIdx.x*16;
    int pm = blockIdx.y; int p = pm/9, m = pm - 9*p; int l = c_deg[m];
    __shared__ __align__(16) float xs[16*64];
    int tid = threadIdx.x; // 256
    for (int i = tid; i < 1024; i += 256){
        int nn = i>>6, f = i&63; int n = n0+nn;
        xs[i] = (n < NN) ? g_att[((size_t)(n*PP+p)*MM+m)*FF + f] : 0.f;
    }
    __syncthreads();
    int g = tid&63, nb = tid>>6;
    const ulonglong2* wo = (const ulonglong2*)&g_WoT[(size_t)(p*3+l)*4096 + g*64];
    u64 acc[4] = {0,0,0,0};
    for (int f4 = 0; f4 < 16; f4++){
        ulonglong2 wv = wo[f4];
        #pragma unroll
        for (int j = 0; j < 4; j++){
            ulonglong2 x = *(const ulonglong2*)&xs[(nb+4*j)*64 + f4*4];
            fma2(acc[j], x.x, wv.x); fma2(acc[j], x.y, wv.y);
        }
    }
    #pragma unroll
    for (int j = 0; j < 4; j++){
        int n = n0 + nb + 4*j;
        if (n < NN){
            float mc = g_sumcut[n] / fmaxf(g_cnt[n], 1.f);
            int idx = ((n*PP+p)*MM+m)*FF + g;
            float post = (mc < 1e-5f) ? g_xpre[idx] : hsum2(acc[j]);
            float a1 = g_c[(size_t)n*CDIM + OFF_A1 + (p*3+l)*64 + g];
            g_x1[idx] = fn[idx] + a1*post;
        }
    }
}

// ---------------- gelu-ratio gate from h[:,0,0,:] ----------------
__global__ void k_gate(){
    int n = blockIdx.x;
    __shared__ __align__(16) float xs[64];
    int tid = threadIdx.x; // 256
    if (tid < 64) xs[tid] = g_xpre2[(size_t)n*1152 + tid];
    __syncthreads();
    const ulonglong2* wt = (const ulonglong2*)&g_W1T[(size_t)tid*64];
    u64 acc = 0ull;
    for (int f4 = 0; f4 < 16; f4++){
        ulonglong2 wv = wt[f4];
        ulonglong2 x = *(const ulonglong2*)&xs[f4*4];
        fma2(acc, x.x, wv.x); fma2(acc, x.y, wv.y);
    }
    float s = hsum2(acc);
    float t = tanhf(0.7978845608028654f*(s + 0.044715f*s*s*s));
    g_gate[(size_t)n*NF + tid] = 0.5f*(1.f + t);
}

// ---------------- fused MLP: (X@W1)*gate -> @W2 -> gate(a2) + residual ----------------
__global__ void __launch_bounds__(256) k_mlp(float* __restrict__ out){
    int n0 = blockIdx.x*16;
    int pm = blockIdx.y; int p = pm/9, m = pm - 9*p; int l = c_deg[m];
    __shared__ __align__(16) float xs[16*64];
    __shared__ __align__(16) float hs[16*256];
    int tid = threadIdx.x; // 256
    for (int i = tid; i < 1024; i += 256){
        int nn = i>>6, f = i&63; int n = n0+nn;
        xs[i] = (n < NN) ? g_xpre2[((size_t)(n*PP+p)*MM+m)*FF + f] : 0.f;
    }
    __syncthreads();
    {
        const ulonglong2* w1 = (const ulonglong2*)&g_W1T[(size_t)(p*3+l)*16384 + tid*64];
        u64 acc[16];
        #pragma unroll
        for (int nn = 0; nn < 16; nn++) acc[nn] = 0ull;
        for (int f4 = 0; f4 < 16; f4++){
            ulonglong2 wv = w1[f4];
            #pragma unroll
            for (int nn = 0; nn < 16; nn++){
                ulonglong2 x = *(const ulonglong2*)&xs[nn*64 + f4*4];
                fma2(acc[nn], x.x, wv.x); fma2(acc[nn], x.y, wv.y);
            }
        }
        #pragma unroll
        for (int nn = 0; nn < 16; nn++){
            int n = n0+nn;
            float gt = (n < NN) ? g_gate[(size_t)n*NF + tid] : 0.f;
            hs[nn*256 + tid] = hsum2(acc[nn])*gt;
        }
    }
    __syncthreads();
    int g = tid&63, nb = tid>>6;
    const ulonglong2* w2 = (const ulonglong2*)&g_W2T[(size_t)(p*3+l)*16384 + g*256];
    u64 a2acc[4] = {0,0,0,0};
    for (int jj4 = 0; jj4 < 64; jj4++){
        ulonglong2 wv = w2[jj4];
        #pragma unroll
        for (int k2 = 0; k2 < 4; k2++){
            ulonglong2 hv = *(const ulonglong2*)&hs[(nb+4*k2)*256 + jj4*4];
            fma2(a2acc[k2], hv.x, wv.x); fma2(a2acc[k2], hv.y, wv.y);
        }
    }
    #pragma unroll
    for (int k2 = 0; k2 < 4; k2++){
        int n = n0 + nb + 4*k2;
        if (n < NN){
            int idx = ((n*PP+p)*MM+m)*FF + g;
            float a2 = g_c[(size_t)n*CDIM + OFF_A2 + (p*3+l)*64 + g];
            out[idx] = g_x1[idx] + a2*hsum2(a2acc[k2]);
        }
    }
}

extern "C" void kernel_launch(void* const* d_in, const int* in_sizes, int n_in,
                              void* d_out, int out_size){
    const float* fn    = (const float*)d_in[0];
    const float* fe    = (const float*)d_in[1];
    const float* ft    = (const float*)d_in[2];
    const float* cut   = (const float*)d_in[3];
    const float* lns   = (const float*)d_in[4];
    const float* lnb   = (const float*)d_in[5];
    const float* Wc    = (const float*)d_in[6];
    const float* bc    = (const float*)d_in[7];
    const float* Wq    = (const float*)d_in[8];
    const float* Wk    = (const float*)d_in[9];
    const float* Wv    = (const float*)d_in[10];
    const float* Wo    = (const float*)d_in[11];
    const float* Weqk  = (const float*)d_in[12];
    const float* Wev   = (const float*)d_in[13];
    const float* W1    = (const float*)d_in[14];
    const float* W2    = (const float*)d_in[15];
    const int*   src   = (const int*)d_in[16];
    const int*   dst   = (const int*)d_in[17];
    float* out = (float*)d_out;

    k_init<<<(NPMF+255)/256, 256>>>();
    k_tr_qkvo<<<dim3(18,4), 256>>>(Wq, Wk, Wv, Wo);
    k_tr_e<<<2, 256>>>(Weqk, Wev);
    k_tr_w1<<<18, 256>>>(W1);
    k_tr_w2<<<18, 256>>>(W2);
    k_tr_wc<<<(64*CDIM+255)/256, 256>>>(Wc);
    k_timecond<<<NN/8, 256>>>(ft, lns, lnb, bc);
    k_ln_mod<0><<<NN, 192>>>(fn);
    dim3 gpm((NN+15)/16, PP*MM);
    k_qkv<<<gpm, 256>>>();
    k_logits<<<NE, 128>>>(fe, src, dst);
    k_softmax_w<<<(NE+255)/256, 256>>>(dst, cut);
    k_scatter<<<NE, 128>>>(fe, src, dst);
    k_out_res<<<gpm, 256>>>(fn);
    k_ln_mod<1><<<NN, 192>>>(fn);
    k_gate<<<NN, 256>>>();
    k_mlp<<<gpm, 256>>>(out);
}

// round 5
// speedup vs baseline: 2.4069x; 2.4069x over previous
#include <cuda_runtime.h>
#include <math.h>

#define NN 6000
#define NE 72000
#define PP 2
#define MM 9
#define FF 64
#define HH 4
#define CDIM 1664
#define NF 256
#define NPMF (NN*PP*MM*FF)

#define OFF_G1 0
#define OFF_B1 384
#define OFF_A1 448
#define OFF_G2 832
#define OFF_B2 1216
#define OFF_A2 1280

__constant__ int c_deg[9] = {0,1,1,1,2,2,2,2,2};

// ---- scratch (static device globals; no runtime allocation) ----
__device__ float    g_c[NN*CDIM];
__device__ __align__(16) float g_xpre[NPMF];
__device__ __align__(16) float g_q[NPMF];
__device__ __align__(16) float g_k[NPMF];
__device__ __align__(16) float g_v[NPMF];
__device__ float    g_logits[NE*HH];
__device__ unsigned g_lmax[NN*HH];
__device__ float    g_w[NE*HH];
__device__ __align__(16) float g_denom[NN*HH];
__device__ __align__(8)  float2 g_sc2[NN];     // {sumcut, cnt}
__device__ __align__(16) float g_att[NPMF];
__device__ float    g_x1[NPMF];
__device__ __align__(16) float g_xpre2[NPMF];
__device__ float    g_gate[NN*NF];

__device__ __forceinline__ unsigned flipf(float f){
    unsigned u = __float_as_uint(f);
    return (u & 0x80000000u) ? ~u : (u | 0x80000000u);
}
__device__ __forceinline__ float unflipf(unsigned u){
    return __uint_as_float((u & 0x80000000u) ? (u ^ 0x80000000u) : ~u);
}

// ---------------- init ----------------
__global__ void k_init(){
    int i = blockIdx.x*256 + threadIdx.x;
    if (i < NPMF) g_att[i] = 0.f;
    if (i < NN*HH){ g_denom[i] = 0.f; g_lmax[i] = 0u; }
    if (i < NN){ g_sc2[i] = make_float2(0.f, 0.f); }
}

// ---------------- time conditioning: LN(T) -> silu -> @W_c + b_c ----------------
__global__ void k_timecond(const float* __restrict__ ft, const float* __restrict__ scale,
                           const float* __restrict__ bias, const float* __restrict__ Wc,
                           const float* __restrict__ bc){
    __shared__ __align__(16) float s[8][64];
    int n0 = blockIdx.x*8;
    int tid = threadIdx.x; // 256
    for (int i = tid; i < 512; i += 256){
        int nn = i>>6, f = i&63; int n = n0+nn;
        s[nn][f] = (n < NN) ? ft[n*64+f] : 0.f;
    }
    __syncthreads();
    int w = tid>>5, lane = tid&31; // warp w handles node w
    {
        float v0 = s[w][lane], v1 = s[w][lane+32];
        float sum = v0+v1, sq = v0*v0 + v1*v1;
        #pragma unroll
        for (int o = 16; o; o >>= 1){
            sum += __shfl_xor_sync(0xffffffffu, sum, o);
            sq  += __shfl_xor_sync(0xffffffffu, sq , o);
        }
        float mu = sum*(1.f/64.f);
        float var = sq*(1.f/64.f) - mu*mu;
        float rstd = rsqrtf(var + 1e-6f);
        float c0 = (v0-mu)*rstd*scale[lane]    + bias[lane];
        float c1 = (v1-mu)*rstd*scale[lane+32] + bias[lane+32];
        s[w][lane]    = c0 / (1.f + __expf(-c0));
        s[w][lane+32] = c1 / (1.f + __expf(-c1));
    }
    __syncthreads();
    for (int j = tid; j < CDIM; j += 256){
        float acc[8];
        float bb = bc[j];
        #pragma unroll
        for (int nn = 0; nn < 8; nn++) acc[nn] = bb;
        for (int t = 0; t < 64; t += 4){
            float w0 = Wc[(t  )*CDIM+j], w1 = Wc[(t+1)*CDIM+j];
            float w2 = Wc[(t+2)*CDIM+j], w3 = Wc[(t+3)*CDIM+j];
            #pragma unroll
            for (int nn = 0; nn < 8; nn++){
                float4 x = *(const float4*)&s[nn][t];
                acc[nn] += x.x*w0 + x.y*w1 + x.z*w2 + x.w*w3;
            }
        }
        #pragma unroll
        for (int nn = 0; nn < 8; nn++){
            int n = n0+nn;
            if (n < NN) g_c[(size_t)n*CDIM + j] = acc[nn];
        }
    }
}

// ---------------- equivariant LN + modulate ----------------
template<int PASS>
__global__ void k_ln_mod(const float* __restrict__ fn){
    int n = blockIdx.x;
    const float* xin  = PASS ? g_x1 : fn;
    float*       xout = PASS ? g_xpre2 : g_xpre;
    const int offG = PASS ? OFF_G2 : OFF_G1;
    const int offB = PASS ? OFF_B2 : OFF_B1;
    __shared__ float sm[1152];
    __shared__ float s_inv[2][3];
    __shared__ float s_mean[2];
    int tid = threadIdx.x; // 192
    for (int i = tid; i < 1152; i += 192) sm[i] = xin[(size_t)n*1152 + i];
    __syncthreads();
    int w = tid>>5, lane = tid&31;   // 6 warps = (p,l) pairs
    int p = w/3, l = w - 3*p;
    int base = p*576 + l*l*64;
    int cnt = (2*l+1)*64;
    float ss = 0.f, s1 = 0.f;
    for (int i = lane; i < cnt; i += 32){ float v = sm[base+i]; ss += v*v; s1 += v; }
    #pragma unroll
    for (int o = 16; o; o >>= 1){
        ss += __shfl_xor_sync(0xffffffffu, ss, o);
        s1 += __shfl_xor_sync(0xffffffffu, s1, o);
    }
    if (lane == 0){
        if (l == 0){ float mean = s1*(1.f/64.f); s_mean[p] = mean; ss -= 64.f*mean*mean; }
        s_inv[p][l] = rsqrtf(ss/(float)cnt + 1e-6f);
    }
    __syncthreads();
    const float* cc = g_c + (size_t)n*CDIM;
    for (int i = tid; i < 1152; i += 192){
        int p2 = i/576; int r = i - 576*p2; int m = r>>6; int f = r&63;
        int l2 = c_deg[m];
        float v = sm[i];
        if (m == 0) v -= s_mean[p2];
        float gmod = cc[offG + (p2*3+l2)*64 + f];
        float y = v * s_inv[p2][l2] * (1.f + gmod);
        if (m == 0) y += cc[offB + f];
        xout[(size_t)n*1152 + i] = y;
    }
}

// ---------------- QKV projections (deg_dense), 16 nodes per block per (p,m) ----------------
__global__ void k_qkv(const float* __restrict__ Wq, const float* __restrict__ Wk,
                      const float* __restrict__ Wv){
    int n0 = blockIdx.x*16;
    int pm = blockIdx.y; int p = pm/9, m = pm - 9*p; int l = c_deg[m];
    __shared__ __align__(16) float xs[16*64];
    int tid = threadIdx.x; // 256
    for (int i = tid; i < 1024; i += 256){
        int nn = i>>6, f = i&63; int n = n0+nn;
        xs[i] = (n < NN) ? g_xpre[((size_t)(n*PP+p)*MM+m)*FF + f] : 0.f;
    }
    __syncthreads();
    int g = tid&63, nb = tid>>6;
    const float* wq = Wq + (size_t)(p*3+l)*4096;
    const float* wk = Wk + (size_t)(p*3+l)*4096;
    const float* wv = Wv + (size_t)(p*3+l)*4096;
    float aq[4] = {0,0,0,0}, ak[4] = {0,0,0,0}, av[4] = {0,0,0,0};
    for (int f = 0; f < 64; f += 4){
        float q0=wq[f*64+g], q1=wq[(f+1)*64+g], q2=wq[(f+2)*64+g], q3=wq[(f+3)*64+g];
        float k0=wk[f*64+g], k1=wk[(f+1)*64+g], k2=wk[(f+2)*64+g], k3=wk[(f+3)*64+g];
        float v0=wv[f*64+g], v1=wv[(f+1)*64+g], v2=wv[(f+2)*64+g], v3=wv[(f+3)*64+g];
        #pragma unroll
        for (int j = 0; j < 4; j++){
            float4 x = *(const float4*)&xs[(nb+4*j)*64 + f];
            aq[j] += x.x*q0 + x.y*q1 + x.z*q2 + x.w*q3;
            ak[j] += x.x*k0 + x.y*k1 + x.z*k2 + x.w*k3;
            av[j] += x.x*v0 + x.y*v1 + x.z*v2 + x.w*v3;
        }
    }
    #pragma unroll
    for (int j = 0; j < 4; j++){
        int n = n0 + nb + 4*j;
        if (n < NN){
            int idx = ((n*PP+p)*MM+m)*FF + g;
            g_q[idx] = aq[j]; g_k[idx] = ak[j]; g_v[idx] = av[j];
        }
    }
}

// ---------------- per-edge: e_qk projection + logits + segment max ----------------
__global__ void k_logits(const float* __restrict__ fe, const float* __restrict__ Weqk,
                         const int* __restrict__ src, const int* __restrict__ dst){
    int e = blockIdx.x;
    __shared__ __align__(16) float sfe[576];
    __shared__ __align__(16) float seqk[576];
    int tid = threadIdx.x; // 128
    const float4* fp = (const float4*)(fe + (size_t)e*576);
    for (int i = tid; i < 144; i += 128) ((float4*)sfe)[i] = fp[i];
    __syncthreads();
    {
        int g = tid&63, half = tid>>6;
        int m0 = half*5;
        float acc[5] = {0,0,0,0,0};
        for (int f = 0; f < 64; f += 4){
            float w0=Weqk[f*64+g], w1=Weqk[(f+1)*64+g], w2=Weqk[(f+2)*64+g], w3=Weqk[(f+3)*64+g];
            #pragma unroll
            for (int mi = 0; mi < 5; mi++){
                int m = m0+mi;
                if (m < 9){
                    float4 x = *(const float4*)&sfe[m*64+f];
                    acc[mi] += x.x*w0 + x.y*w1 + x.z*w2 + x.w*w3;
                }
            }
        }
        #pragma unroll
        for (int mi = 0; mi < 5; mi++){
            int m = m0+mi;
            if (m < 9) seqk[m*64+g] = acc[mi];
        }
    }
    __syncthreads();
    int h = tid>>5, lane = tid&31;
    int s = src[e], d = dst[e];
    float acc = 0.f;
    int f = h*16 + (lane&15);
    for (int pm = (lane>>4); pm < 18; pm += 2){
        int p = pm/9, m = pm - 9*p;
        int off = ((p)*MM+m)*FF + f;
        acc += g_q[(size_t)d*1152 + off] * g_k[(size_t)s*1152 + off] * seqk[m*64+f];
    }
    #pragma unroll
    for (int o = 16; o; o >>= 1) acc += __shfl_xor_sync(0xffffffffu, acc, o);
    if (lane == 0){
        float lg = acc * 0.05892556509887896f;  // 1/sqrt(288)
        g_logits[e*HH + h] = lg;
        atomicMax(&g_lmax[d*HH + h], flipf(lg));
    }
}

// ---------------- softmax weights + segment sums (vectorized reds) ----------------
__global__ void k_softmax_w(const int* __restrict__ dst, const float* __restrict__ cutoff){
    int e = blockIdx.x*256 + threadIdx.x;
    if (e >= NE) return;
    int d = dst[e];
    float cut = cutoff[e];
    float wv[HH];
    #pragma unroll
    for (int h = 0; h < HH; h++){
        float lg = g_logits[e*HH + h];
        float lm = unflipf(g_lmax[d*HH + h]);
        wv[h] = __expf(lg - lm) * cut;
        g_w[e*HH + h] = wv[h];
    }
    asm volatile("red.global.add.v4.f32 [%0], {%1,%2,%3,%4};"
                 :: "l"(&g_denom[d*HH]), "f"(wv[0]), "f"(wv[1]), "f"(wv[2]), "f"(wv[3])
                 : "memory");
    asm volatile("red.global.add.v2.f32 [%0], {%1,%2};"
                 :: "l"(&g_sc2[d]), "f"(cut), "f"(1.0f) : "memory");
}

// ---------------- per-edge: e_v projection + attn*v scatter (v4 red) ----------------
__global__ void k_scatter(const float* __restrict__ fe, const float* __restrict__ Wev,
                          const int* __restrict__ src, const int* __restrict__ dst){
    int e = blockIdx.x;
    __shared__ __align__(16) float sfe[576];
    __shared__ __align__(16) float sev[576];
    __shared__ float satt[4];
    int tid = threadIdx.x; // 128
    const float4* fp = (const float4*)(fe + (size_t)e*576);
    for (int i = tid; i < 144; i += 128) ((float4*)sfe)[i] = fp[i];
    int d = dst[e], s = src[e];
    if (tid < 4) satt[tid] = g_w[e*HH + tid] / (g_denom[d*HH + tid] + 1e-9f);
    __syncthreads();
    {
        int g = tid&63, half = tid>>6;
        int m0 = half*5;
        float acc[5] = {0,0,0,0,0};
        for (int f = 0; f < 64; f += 4){
            float w0=Wev[f*64+g], w1=Wev[(f+1)*64+g], w2=Wev[(f+2)*64+g], w3=Wev[(f+3)*64+g];
            #pragma unroll
            for (int mi = 0; mi < 5; mi++){
                int m = m0+mi;
                if (m < 9){
                    float4 x = *(const float4*)&sfe[m*64+f];
                    acc[mi] += x.x*w0 + x.y*w1 + x.z*w2 + x.w*w3;
                }
            }
        }
        #pragma unroll
        for (int mi = 0; mi < 5; mi++){
            int m = m0+mi;
            if (m < 9) sev[m*64+g] = acc[mi];
        }
    }
    __syncthreads();
    for (int i4 = tid; i4 < 288; i4 += 128){
        int i = i4*4;
        int p = i/576; int r = i - 576*p; int m = r>>6; int f = r&63; int h = f>>4;
        float4 vv = *(const float4*)&g_v[((size_t)(s*PP+p)*MM+m)*FF + f];
        float4 ev = *(const float4*)&sev[m*64+f];
        float a = satt[h];
        float* op = &g_att[((size_t)(d*PP+p)*MM+m)*FF + f];
        float r0 = a*vv.x*ev.x, r1 = a*vv.y*ev.y, r2 = a*vv.z*ev.z, r3 = a*vv.w*ev.w;
        asm volatile("red.global.add.v4.f32 [%0], {%1,%2,%3,%4};"
                     :: "l"(op), "f"(r0), "f"(r1), "f"(r2), "f"(r3) : "memory");
    }
}

// ---------------- Wo projection + mean_cut select + residual 1 ----------------
__global__ void k_out_res(const float* __restrict__ fn, const float* __restrict__ Wo){
    int n0 = blockIdx.x*16;
    int pm = blockIdx.y; int p = pm/9, m = pm - 9*p; int l = c_deg[m];
    __shared__ __align__(16) float xs[16*64];
    int tid = threadIdx.x; // 256
    for (int i = tid; i < 1024; i += 256){
        int nn = i>>6, f = i&63; int n = n0+nn;
        xs[i] = (n < NN) ? g_att[((size_t)(n*PP+p)*MM+m)*FF + f] : 0.f;
    }
    __syncthreads();
    int g = tid&63, nb = tid>>6;
    const float* wo = Wo + (size_t)(p*3+l)*4096;
    float acc[4] = {0,0,0,0};
    for (int f = 0; f < 64; f += 4){
        float w0=wo[f*64+g], w1=wo[(f+1)*64+g], w2=wo[(f+2)*64+g], w3=wo[(f+3)*64+g];
        #pragma unroll
        for (int j = 0; j < 4; j++){
            float4 x = *(const float4*)&xs[(nb+4*j)*64 + f];
            acc[j] += x.x*w0 + x.y*w1 + x.z*w2 + x.w*w3;
        }
    }
    #pragma unroll
    for (int j = 0; j < 4; j++){
        int n = n0 + nb + 4*j;
        if (n < NN){
            float2 sc = g_sc2[n];
            float mc = sc.x / fmaxf(sc.y, 1.f);
            int idx = ((n*PP+p)*MM+m)*FF + g;
            float post = (mc < 1e-5f) ? g_xpre[idx] : acc[j];
            float a1 = g_c[(size_t)n*CDIM + OFF_A1 + (p*3+l)*64 + g];
            g_x1[idx] = fn[idx] + a1*post;
        }
    }
}

// ---------------- gelu-ratio gate from h[:,0,0,:] ----------------
__global__ void k_gate(const float* __restrict__ W1){
    int n = blockIdx.x;
    __shared__ __align__(16) float xs[64];
    int tid = threadIdx.x; // 256
    if (tid < 64) xs[tid] = g_xpre2[(size_t)n*1152 + tid]; // p=0,m=0 row
    __syncthreads();
    float acc = 0.f;
    for (int f = 0; f < 64; f += 4){
        float4 x = *(const float4*)&xs[f];
        acc += x.x*W1[f*256+tid] + x.y*W1[(f+1)*256+tid]
             + x.z*W1[(f+2)*256+tid] + x.w*W1[(f+3)*256+tid];
    }
    float s = acc;
    float t = tanhf(0.7978845608028654f*(s + 0.044715f*s*s*s));
    g_gate[(size_t)n*NF + tid] = 0.5f*(1.f + t);  // gelu(s)/s (tanh approx), ==0.5 at s=0
}

// ---------------- fused MLP: (X@W1)*gate -> @W2 -> gate(a2) + residual ----------------
__global__ void __launch_bounds__(256) k_mlp(const float* __restrict__ W1, const float* __restrict__ W2,
                      float* __restrict__ out){
    int n0 = blockIdx.x*16;
    int pm = blockIdx.y; int p = pm/9, m = pm - 9*p; int l = c_deg[m];
    __shared__ __align__(16) float xs[16*64];
    __shared__ __align__(16) float hs[16*256];
    int tid = threadIdx.x; // 256
    for (int i = tid; i < 1024; i += 256){
        int nn = i>>6, f = i&63; int n = n0+nn;
        xs[i] = (n < NN) ? g_xpre2[((size_t)(n*PP+p)*MM+m)*FF + f] : 0.f;
    }
    __syncthreads();
    const float* w1 = W1 + (size_t)(p*3+l)*64*256;
    float acc[16];
    #pragma unroll
    for (int nn = 0; nn < 16; nn++) acc[nn] = 0.f;
    int j = tid;
    for (int f = 0; f < 64; f += 4){
        float w0=w1[f*256+j], wA=w1[(f+1)*256+j], wB=w1[(f+2)*256+j], wC=w1[(f+3)*256+j];
        #pragma unroll
        for (int nn = 0; nn < 16; nn++){
            float4 x = *(const float4*)&xs[nn*64 + f];
            acc[nn] += x.x*w0 + x.y*wA + x.z*wB + x.w*wC;
        }
    }
    #pragma unroll
    for (int nn = 0; nn < 16; nn++){
        int n = n0+nn;
        float gt = (n < NN) ? g_gate[(size_t)n*NF + j] : 0.f;
        hs[nn*256 + j] = acc[nn]*gt;
    }
    __syncthreads();
    const float* w2 = W2 + (size_t)(p*3+l)*256*64;
    int g = tid&63, nb = tid>>6;
    float a2acc[4] = {0,0,0,0};
    for (int jj = 0; jj < 256; jj += 4){
        float w0=w2[jj*64+g], wA=w2[(jj+1)*64+g], wB=w2[(jj+2)*64+g], wC=w2[(jj+3)*64+g];
        #pragma unroll
        for (int k2 = 0; k2 < 4; k2++){
            float4 hv = *(const float4*)&hs[(nb+4*k2)*256 + jj];
            a2acc[k2] += hv.x*w0 + hv.y*wA + hv.z*wB + hv.w*wC;
        }
    }
    #pragma unroll
    for (int k2 = 0; k2 < 4; k2++){
        int n = n0 + nb + 4*k2;
        if (n < NN){
            int idx = ((n*PP+p)*MM+m)*FF + g;
            float a2 = g_c[(size_t)n*CDIM + OFF_A2 + (p*3+l)*64 + g];
            out[idx] = g_x1[idx] + a2*a2acc[k2];
        }
    }
}

extern "C" void kernel_launch(void* const* d_in, const int* in_sizes, int n_in,
                              void* d_out, int out_size){
    const float* fn    = (const float*)d_in[0];
    const float* fe    = (const float*)d_in[1];
    const float* ft    = (const float*)d_in[2];
    const float* cut   = (const float*)d_in[3];
    const float* lns   = (const float*)d_in[4];
    const float* lnb   = (const float*)d_in[5];
    const float* Wc    = (const float*)d_in[6];
    const float* bc    = (const float*)d_in[7];
    const float* Wq    = (const float*)d_in[8];
    const float* Wk    = (const float*)d_in[9];
    const float* Wv    = (const float*)d_in[10];
    const float* Wo    = (const float*)d_in[11];
    const float* Weqk  = (const float*)d_in[12];
    const float* Wev   = (const float*)d_in[13];
    const float* W1    = (const float*)d_in[14];
    const float* W2    = (const float*)d_in[15];
    const int*   src   = (const int*)d_in[16];
    const int*   dst   = (const int*)d_in[17];
    float* out = (float*)d_out;

    k_init<<<(NPMF+255)/256, 256>>>();
    k_timecond<<<NN/8, 256>>>(ft, lns, lnb, Wc, bc);
    k_ln_mod<0><<<NN, 192>>>(fn);
    dim3 gpm((NN+15)/16, PP*MM);
    k_qkv<<<gpm, 256>>>(Wq, Wk, Wv);
    k_logits<<<NE, 128>>>(fe, Weqk, src, dst);
    k_softmax_w<<<(NE+255)/256, 256>>>(dst, cut);
    k_scatter<<<NE, 128>>>(fe, Wev, src, dst);
    k_out_res<<<gpm, 256>>>(fn, Wo);
    k_ln_mod<1><<<NN, 192>>>(fn);
    k_gate<<<NN, 256>>>(W1);
    k_mlp<<<gpm, 256>>>(W1, W2, out);
}

// round 6
// speedup vs baseline: 2.5725x; 1.0688x over previous
#include <cuda_runtime.h>
#include <math.h>

#define NN 6000
#define NE 72000
#define PP 2
#define MM 9
#define FF 64
#define HH 4
#define CDIM 1664
#define NF 256
#define NPMF (NN*PP*MM*FF)

#define OFF_G1 0
#define OFF_B1 384
#define OFF_A1 448
#define OFF_G2 832
#define OFF_B2 1216
#define OFF_A2 1280

__constant__ int c_deg[9] = {0,1,1,1,2,2,2,2,2};

// ---- scratch (static device globals; no runtime allocation) ----
__device__ float    g_c[NN*CDIM];
__device__ __align__(16) float g_xpre[NPMF];
__device__ __align__(16) float g_q[NPMF];
__device__ __align__(16) float g_k[NPMF];
__device__ __align__(16) float g_v[NPMF];
__device__ float    g_logits[NE*HH];
__device__ unsigned g_lmax[NN*HH];
__device__ float    g_w[NE*HH];
__device__ __align__(16) float g_denom[NN*HH];
__device__ __align__(8)  float2 g_sc2[NN];     // {sumcut, cnt}
__device__ __align__(16) float g_att[NPMF];
__device__ float    g_x1[NPMF];
__device__ __align__(16) float g_xpre2[NPMF];
__device__ float    g_gate[NN*NF];

__device__ __forceinline__ unsigned flipf(float f){
    unsigned u = __float_as_uint(f);
    return (u & 0x80000000u) ? ~u : (u | 0x80000000u);
}
__device__ __forceinline__ float unflipf(unsigned u){
    return __uint_as_float((u & 0x80000000u) ? (u ^ 0x80000000u) : ~u);
}

// ---------------- init ----------------
__global__ void k_init(){
    int i = blockIdx.x*256 + threadIdx.x;
    if (i < NPMF) g_att[i] = 0.f;
    if (i < NN*HH){ g_denom[i] = 0.f; g_lmax[i] = 0u; }
    if (i < NN){ g_sc2[i] = make_float2(0.f, 0.f); }
}

// ---------------- time conditioning: LN(T) -> silu -> @W_c + b_c ----------------
__global__ void k_timecond(const float* __restrict__ ft, const float* __restrict__ scale,
                           const float* __restrict__ bias, const float* __restrict__ Wc,
                           const float* __restrict__ bc){
    __shared__ __align__(16) float s[8][64];
    int n0 = blockIdx.x*8;
    int tid = threadIdx.x; // 256
    for (int i = tid; i < 512; i += 256){
        int nn = i>>6, f = i&63; int n = n0+nn;
        s[nn][f] = (n < NN) ? ft[n*64+f] : 0.f;
    }
    __syncthreads();
    int w = tid>>5, lane = tid&31;
    {
        float v0 = s[w][lane], v1 = s[w][lane+32];
        float sum = v0+v1, sq = v0*v0 + v1*v1;
        #pragma unroll
        for (int o = 16; o; o >>= 1){
            sum += __shfl_xor_sync(0xffffffffu, sum, o);
            sq  += __shfl_xor_sync(0xffffffffu, sq , o);
        }
        float mu = sum*(1.f/64.f);
        float var = sq*(1.f/64.f) - mu*mu;
        float rstd = rsqrtf(var + 1e-6f);
        float c0 = (v0-mu)*rstd*scale[lane]    + bias[lane];
        float c1 = (v1-mu)*rstd*scale[lane+32] + bias[lane+32];
        s[w][lane]    = c0 / (1.f + __expf(-c0));
        s[w][lane+32] = c1 / (1.f + __expf(-c1));
    }
    __syncthreads();
    for (int j = tid; j < CDIM; j += 256){
        float acc[8];
        float bb = bc[j];
        #pragma unroll
        for (int nn = 0; nn < 8; nn++) acc[nn] = bb;
        for (int t = 0; t < 64; t += 4){
            float w0 = Wc[(t  )*CDIM+j], w1 = Wc[(t+1)*CDIM+j];
            float w2 = Wc[(t+2)*CDIM+j], w3 = Wc[(t+3)*CDIM+j];
            #pragma unroll
            for (int nn = 0; nn < 8; nn++){
                float4 x = *(const float4*)&s[nn][t];
                acc[nn] += x.x*w0 + x.y*w1 + x.z*w2 + x.w*w3;
            }
        }
        #pragma unroll
        for (int nn = 0; nn < 8; nn++){
            int n = n0+nn;
            if (n < NN) g_c[(size_t)n*CDIM + j] = acc[nn];
        }
    }
}

// ---------------- equivariant LN + modulate ----------------
template<int PASS>
__global__ void k_ln_mod(const float* __restrict__ fn){
    int n = blockIdx.x;
    const float* xin  = PASS ? g_x1 : fn;
    float*       xout = PASS ? g_xpre2 : g_xpre;
    const int offG = PASS ? OFF_G2 : OFF_G1;
    const int offB = PASS ? OFF_B2 : OFF_B1;
    __shared__ float sm[1152];
    __shared__ float s_inv[2][3];
    __shared__ float s_mean[2];
    int tid = threadIdx.x; // 192
    for (int i = tid; i < 1152; i += 192) sm[i] = xin[(size_t)n*1152 + i];
    __syncthreads();
    int w = tid>>5, lane = tid&31;   // 6 warps = (p,l) pairs
    int p = w/3, l = w - 3*p;
    int base = p*576 + l*l*64;
    int cnt = (2*l+1)*64;
    float ss = 0.f, s1 = 0.f;
    for (int i = lane; i < cnt; i += 32){ float v = sm[base+i]; ss += v*v; s1 += v; }
    #pragma unroll
    for (int o = 16; o; o >>= 1){
        ss += __shfl_xor_sync(0xffffffffu, ss, o);
        s1 += __shfl_xor_sync(0xffffffffu, s1, o);
    }
    if (lane == 0){
        if (l == 0){ float mean = s1*(1.f/64.f); s_mean[p] = mean; ss -= 64.f*mean*mean; }
        s_inv[p][l] = rsqrtf(ss/(float)cnt + 1e-6f);
    }
    __syncthreads();
    const float* cc = g_c + (size_t)n*CDIM;
    for (int i = tid; i < 1152; i += 192){
        int p2 = i/576; int r = i - 576*p2; int m = r>>6; int f = r&63;
        int l2 = c_deg[m];
        float v = sm[i];
        if (m == 0) v -= s_mean[p2];
        float gmod = cc[offG + (p2*3+l2)*64 + f];
        float y = v * s_inv[p2][l2] * (1.f + gmod);
        if (m == 0) y += cc[offB + f];
        xout[(size_t)n*1152 + i] = y;
    }
}

// ---------------- QKV projections: 32 nodes/block, 8 nodes/thread ----------------
__global__ void __launch_bounds__(256) k_qkv(const float* __restrict__ Wq, const float* __restrict__ Wk,
                      const float* __restrict__ Wv){
    int n0 = blockIdx.x*32;
    int pm = blockIdx.y; int p = pm/9, m = pm - 9*p; int l = c_deg[m];
    __shared__ __align__(16) float xs[32*64];
    int tid = threadIdx.x; // 256
    for (int i = tid; i < 2048; i += 256){
        int nn = i>>6, f = i&63; int n = n0+nn;
        xs[i] = (n < NN) ? g_xpre[((size_t)(n*PP+p)*MM+m)*FF + f] : 0.f;
    }
    __syncthreads();
    int g = tid&63, nb = tid>>6;
    const float* wq = Wq + (size_t)(p*3+l)*4096;
    const float* wk = Wk + (size_t)(p*3+l)*4096;
    const float* wv = Wv + (size_t)(p*3+l)*4096;
    float aq[8], ak[8], av[8];
    #pragma unroll
    for (int j = 0; j < 8; j++){ aq[j]=0.f; ak[j]=0.f; av[j]=0.f; }
    for (int f = 0; f < 64; f += 4){
        float q0=wq[f*64+g], q1=wq[(f+1)*64+g], q2=wq[(f+2)*64+g], q3=wq[(f+3)*64+g];
        float k0=wk[f*64+g], k1=wk[(f+1)*64+g], k2=wk[(f+2)*64+g], k3=wk[(f+3)*64+g];
        float v0=wv[f*64+g], v1=wv[(f+1)*64+g], v2=wv[(f+2)*64+g], v3=wv[(f+3)*64+g];
        #pragma unroll
        for (int j = 0; j < 8; j++){
            float4 x = *(const float4*)&xs[(nb*8+j)*64 + f];
            aq[j] += x.x*q0 + x.y*q1 + x.z*q2 + x.w*q3;
            ak[j] += x.x*k0 + x.y*k1 + x.z*k2 + x.w*k3;
            av[j] += x.x*v0 + x.y*v1 + x.z*v2 + x.w*v3;
        }
    }
    #pragma unroll
    for (int j = 0; j < 8; j++){
        int n = n0 + nb*8 + j;
        if (n < NN){
            int idx = ((n*PP+p)*MM+m)*FF + g;
            g_q[idx] = aq[j]; g_k[idx] = ak[j]; g_v[idx] = av[j];
        }
    }
}

// ---------------- per-edge: e_qk projection + logits + segment max (4 edges/block) ----------------
__global__ void __launch_bounds__(128) k_logits(const float* __restrict__ fe, const float* __restrict__ Weqk,
                         const int* __restrict__ src, const int* __restrict__ dst){
    int e0 = blockIdx.x*4;
    __shared__ __align__(16) float sfe[4*576];
    __shared__ __align__(16) float seqk[4*576];
    int tid = threadIdx.x; // 128
    const float4* fp = (const float4*)(fe + (size_t)e0*576);
    for (int i = tid; i < 576; i += 128) ((float4*)sfe)[i] = fp[i];
    __syncthreads();
    {
        int g = tid&63, half = tid>>6;
        int m0 = half*5;
        float acc[4][5];
        #pragma unroll
        for (int e = 0; e < 4; e++)
            #pragma unroll
            for (int mi = 0; mi < 5; mi++) acc[e][mi] = 0.f;
        for (int f = 0; f < 64; f += 4){
            float w0=Weqk[f*64+g], w1=Weqk[(f+1)*64+g], w2=Weqk[(f+2)*64+g], w3=Weqk[(f+3)*64+g];
            #pragma unroll
            for (int e = 0; e < 4; e++){
                #pragma unroll
                for (int mi = 0; mi < 5; mi++){
                    int m = m0+mi;
                    if (m < 9){
                        float4 x = *(const float4*)&sfe[e*576 + m*64+f];
                        acc[e][mi] += x.x*w0 + x.y*w1 + x.z*w2 + x.w*w3;
                    }
                }
            }
        }
        #pragma unroll
        for (int e = 0; e < 4; e++)
            #pragma unroll
            for (int mi = 0; mi < 5; mi++){
                int m = m0+mi;
                if (m < 9) seqk[e*576 + m*64+g] = acc[e][mi];
            }
    }
    __syncthreads();
    int h = tid>>5, lane = tid&31;
    int f = h*16 + (lane&15);
    #pragma unroll
    for (int e = 0; e < 4; e++){
        int s = src[e0+e], d = dst[e0+e];
        float acc = 0.f;
        for (int pm = (lane>>4); pm < 18; pm += 2){
            int p = pm/9, m = pm - 9*p;
            int off = ((p)*MM+m)*FF + f;
            acc += g_q[(size_t)d*1152 + off] * g_k[(size_t)s*1152 + off] * seqk[e*576 + m*64+f];
        }
        #pragma unroll
        for (int o = 16; o; o >>= 1) acc += __shfl_xor_sync(0xffffffffu, acc, o);
        if (lane == 0){
            float lg = acc * 0.05892556509887896f;  // 1/sqrt(288)
            g_logits[(e0+e)*HH + h] = lg;
            atomicMax(&g_lmax[d*HH + h], flipf(lg));
        }
    }
}

// ---------------- softmax weights + segment sums (vectorized reds) ----------------
__global__ void k_softmax_w(const int* __restrict__ dst, const float* __restrict__ cutoff){
    int e = blockIdx.x*256 + threadIdx.x;
    if (e >= NE) return;
    int d = dst[e];
    float cut = cutoff[e];
    float wv[HH];
    #pragma unroll
    for (int h = 0; h < HH; h++){
        float lg = g_logits[e*HH + h];
        float lm = unflipf(g_lmax[d*HH + h]);
        wv[h] = __expf(lg - lm) * cut;
        g_w[e*HH + h] = wv[h];
    }
    asm volatile("red.global.add.v4.f32 [%0], {%1,%2,%3,%4};"
                 :: "l"(&g_denom[d*HH]), "f"(wv[0]), "f"(wv[1]), "f"(wv[2]), "f"(wv[3])
                 : "memory");
    asm volatile("red.global.add.v2.f32 [%0], {%1,%2};"
                 :: "l"(&g_sc2[d]), "f"(cut), "f"(1.0f) : "memory");
}

// ---------------- per-edge: e_v projection + attn*v scatter (4 edges/block, v4 red) ----------------
__global__ void __launch_bounds__(128) k_scatter(const float* __restrict__ fe, const float* __restrict__ Wev,
                          const int* __restrict__ src, const int* __restrict__ dst){
    int e0 = blockIdx.x*4;
    __shared__ __align__(16) float sfe[4*576];
    __shared__ __align__(16) float sev[4*576];
    __shared__ float satt[4][4];
    int tid = threadIdx.x; // 128
    const float4* fp = (const float4*)(fe + (size_t)e0*576);
    for (int i = tid; i < 576; i += 128) ((float4*)sfe)[i] = fp[i];
    if (tid < 16){
        int e = tid>>2, h = tid&3;
        int d = dst[e0+e];
        satt[e][h] = g_w[(e0+e)*HH + h] / (g_denom[d*HH + h] + 1e-9f);
    }
    __syncthreads();
    {
        int g = tid&63, half = tid>>6;
        int m0 = half*5;
        float acc[4][5];
        #pragma unroll
        for (int e = 0; e < 4; e++)
            #pragma unroll
            for (int mi = 0; mi < 5; mi++) acc[e][mi] = 0.f;
        for (int f = 0; f < 64; f += 4){
            float w0=Wev[f*64+g], w1=Wev[(f+1)*64+g], w2=Wev[(f+2)*64+g], w3=Wev[(f+3)*64+g];
            #pragma unroll
            for (int e = 0; e < 4; e++){
                #pragma unroll
                for (int mi = 0; mi < 5; mi++){
                    int m = m0+mi;
                    if (m < 9){
                        float4 x = *(const float4*)&sfe[e*576 + m*64+f];
                        acc[e][mi] += x.x*w0 + x.y*w1 + x.z*w2 + x.w*w3;
                    }
                }
            }
        }
        #pragma unroll
        for (int e = 0; e < 4; e++)
            #pragma unroll
            for (int mi = 0; mi < 5; mi++){
                int m = m0+mi;
                if (m < 9) sev[e*576 + m*64+g] = acc[e][mi];
            }
    }
    __syncthreads();
    #pragma unroll
    for (int e = 0; e < 4; e++){
        int d = dst[e0+e], s = src[e0+e];
        for (int i4 = tid; i4 < 288; i4 += 128){
            int i = i4*4;
            int p = i/576; int r = i - 576*p; int m = r>>6; int f = r&63; int h = f>>4;
            float4 vv = *(const float4*)&g_v[((size_t)(s*PP+p)*MM+m)*FF + f];
            float4 ev = *(const float4*)&sev[e*576 + m*64+f];
            float a = satt[e][h];
            float* op = &g_att[((size_t)(d*PP+p)*MM+m)*FF + f];
            float r0 = a*vv.x*ev.x, r1 = a*vv.y*ev.y, r2 = a*vv.z*ev.z, r3 = a*vv.w*ev.w;
            asm volatile("red.global.add.v4.f32 [%0], {%1,%2,%3,%4};"
                         :: "l"(op), "f"(r0), "f"(r1), "f"(r2), "f"(r3) : "memory");
        }
    }
}

// ---------------- Wo projection + mean_cut select + residual 1 (32 nodes/block) ----------------
__global__ void __launch_bounds__(256) k_out_res(const float* __restrict__ fn, const float* __restrict__ Wo){
    int n0 = blockIdx.x*32;
    int pm = blockIdx.y; int p = pm/9, m = pm - 9*p; int l = c_deg[m];
    __shared__ __align__(16) float xs[32*64];
    int tid = threadIdx.x; // 256
    for (int i = tid; i < 2048; i += 256){
        int nn = i>>6, f = i&63; int n = n0+nn;
        xs[i] = (n < NN) ? g_att[((size_t)(n*PP+p)*MM+m)*FF + f] : 0.f;
    }
    __syncthreads();
    int g = tid&63, nb = tid>>6;
    const float* wo = Wo + (size_t)(p*3+l)*4096;
    float acc[8];
    #pragma unroll
    for (int j = 0; j < 8; j++) acc[j] = 0.f;
    for (int f = 0; f < 64; f += 4){
        float w0=wo[f*64+g], w1=wo[(f+1)*64+g], w2=wo[(f+2)*64+g], w3=wo[(f+3)*64+g];
        #pragma unroll
        for (int j = 0; j < 8; j++){
            float4 x = *(const float4*)&xs[(nb*8+j)*64 + f];
            acc[j] += x.x*w0 + x.y*w1 + x.z*w2 + x.w*w3;
        }
    }
    #pragma unroll
    for (int j = 0; j < 8; j++){
        int n = n0 + nb*8 + j;
        if (n < NN){
            float2 sc = g_sc2[n];
            float mc = sc.x / fmaxf(sc.y, 1.f);
            int idx = ((n*PP+p)*MM+m)*FF + g;
            float post = (mc < 1e-5f) ? g_xpre[idx] : acc[j];
            float a1 = g_c[(size_t)n*CDIM + OFF_A1 + (p*3+l)*64 + g];
            g_x1[idx] = fn[idx] + a1*post;
        }
    }
}

// ---------------- gelu-ratio gate from h[:,0,0,:] ----------------
__global__ void k_gate(const float* __restrict__ W1){
    int n = blockIdx.x;
    __shared__ __align__(16) float xs[64];
    int tid = threadIdx.x; // 256
    if (tid < 64) xs[tid] = g_xpre2[(size_t)n*1152 + tid];
    __syncthreads();
    float acc = 0.f;
    for (int f = 0; f < 64; f += 4){
        float4 x = *(const float4*)&xs[f];
        acc += x.x*W1[f*256+tid] + x.y*W1[(f+1)*256+tid]
             + x.z*W1[(f+2)*256+tid] + x.w*W1[(f+3)*256+tid];
    }
    float s = acc;
    float t = tanhf(0.7978845608028654f*(s + 0.044715f*s*s*s));
    g_gate[(size_t)n*NF + tid] = 0.5f*(1.f + t);
}

// ---------------- fused MLP: 32 nodes/block ----------------
__global__ void __launch_bounds__(256) k_mlp(const float* __restrict__ W1, const float* __restrict__ W2,
                      float* __restrict__ out){
    int n0 = blockIdx.x*32;
    int pm = blockIdx.y; int p = pm/9, m = pm - 9*p; int l = c_deg[m];
    __shared__ __align__(16) float xs[32*64];    // 8 KB
    __shared__ __align__(16) float hs[32*256];   // 32 KB
    int tid = threadIdx.x; // 256
    for (int i = tid; i < 2048; i += 256){
        int nn = i>>6, f = i&63; int n = n0+nn;
        xs[i] = (n < NN) ? g_xpre2[((size_t)(n*PP+p)*MM+m)*FF + f] : 0.f;
    }
    __syncthreads();
    const float* w1 = W1 + (size_t)(p*3+l)*64*256;
    int j = tid;
    #pragma unroll
    for (int h2 = 0; h2 < 2; h2++){
        float acc[16];
        #pragma unroll
        for (int nn = 0; nn < 16; nn++) acc[nn] = 0.f;
        for (int f = 0; f < 64; f += 4){
            float w0=w1[f*256+j], wA=w1[(f+1)*256+j], wB=w1[(f+2)*256+j], wC=w1[(f+3)*256+j];
            #pragma unroll
            for (int nn = 0; nn < 16; nn++){
                float4 x = *(const float4*)&xs[(h2*16+nn)*64 + f];
                acc[nn] += x.x*w0 + x.y*wA + x.z*wB + x.w*wC;
            }
        }
        #pragma unroll
        for (int nn = 0; nn < 16; nn++){
            int n = n0 + h2*16 + nn;
            float gt = (n < NN) ? g_gate[(size_t)n*NF + j] : 0.f;
            hs[(h2*16+nn)*256 + j] = acc[nn]*gt;
        }
    }
    __syncthreads();
    const float* w2 = W2 + (size_t)(p*3+l)*256*64;
    int g = tid&63, nb = tid>>6;
    float a2acc[8];
    #pragma unroll
    for (int k2 = 0; k2 < 8; k2++) a2acc[k2] = 0.f;
    for (int jj = 0; jj < 256; jj += 4){
        float w0=w2[jj*64+g], wA=w2[(jj+1)*64+g], wB=w2[(jj+2)*64+g], wC=w2[(jj+3)*64+g];
        #pragma unroll
        for (int k2 = 0; k2 < 8; k2++){
            float4 hv = *(const float4*)&hs[(nb*8+k2)*256 + jj];
            a2acc[k2] += hv.x*w0 + hv.y*wA + hv.z*wB + hv.w*wC;
        }
    }
    #pragma unroll
    for (int k2 = 0; k2 < 8; k2++){
        int n = n0 + nb*8 + k2;
        if (n < NN){
            int idx = ((n*PP+p)*MM+m)*FF + g;
            float a2 = g_c[(size_t)n*CDIM + OFF_A2 + (p*3+l)*64 + g];
            out[idx] = g_x1[idx] + a2*a2acc[k2];
        }
    }
}

extern "C" void kernel_launch(void* const* d_in, const int* in_sizes, int n_in,
                              void* d_out, int out_size){
    const float* fn    = (const float*)d_in[0];
    const float* fe    = (const float*)d_in[1];
    const float* ft    = (const float*)d_in[2];
    const float* cut   = (const float*)d_in[3];
    const float* lns   = (const float*)d_in[4];
    const float* lnb   = (const float*)d_in[5];
    const float* Wc    = (const float*)d_in[6];
    const float* bc    = (const float*)d_in[7];
    const float* Wq    = (const float*)d_in[8];
    const float* Wk    = (const float*)d_in[9];
    const float* Wv    = (const float*)d_in[10];
    const float* Wo    = (const float*)d_in[11];
    const float* Weqk  = (const float*)d_in[12];
    const float* Wev   = (const float*)d_in[13];
    const float* W1    = (const float*)d_in[14];
    const float* W2    = (const float*)d_in[15];
    const int*   src   = (const int*)d_in[16];
    const int*   dst   = (const int*)d_in[17];
    float* out = (float*)d_out;

    k_init<<<(NPMF+255)/256, 256>>>();
    k_timecond<<<NN/8, 256>>>(ft, lns, lnb, Wc, bc);
    k_ln_mod<0><<<NN, 192>>>(fn);
    dim3 gpm((NN+31)/32, PP*MM);
    k_qkv<<<gpm, 256>>>(Wq, Wk, Wv);
    k_logits<<<NE/4, 128>>>(fe, Weqk, src, dst);
    k_softmax_w<<<(NE+255)/256, 256>>>(dst, cut);
    k_scatter<<<NE/4, 128>>>(fe, Wev, src, dst);
    k_out_res<<<gpm, 256>>>(fn, Wo);
    k_ln_mod<1><<<NN, 192>>>(fn);
    k_gate<<<NN, 256>>>(W1);
    k_mlp<<<gpm, 256>>>(W1, W2, out);
}